// round 1
// baseline (speedup 1.0000x reference)
#include <cuda_runtime.h>
#include <cuda_bf16.h>
#include <cstdint>

#define N_ROWS 4096
#define CIN 128

// ---------------- device scratch (no allocation allowed) ----------------
__device__ float g_v[4][128];        // v1_irr, v2_irr, v1_sol, v2_sol
__device__ float g_c[4];             // score constants
__device__ float g_bias[128];        // Wi_b0+Wi_b1+Ws_b0+Ws_b1+Wh_b
__device__ float g_s[4][N_ROWS];     // s1_irr, s2_irr, s1_sol, s2_sol
__device__ float g_Ldx[N_ROWS * 128];
__device__ float g_Lux[N_ROWS * 128];
__device__ float g_Px[2 * N_ROWS * 128];   // split-K partials
__device__ float g_Mirr[N_ROWS * 128];
__device__ float g_Msol[N_ROWS * 128];
__device__ float g_rowmax[2][N_ROWS];

// ---------------- kernel 1: fold attention vectors + biases ----------------
__global__ void k_prep(const float* __restrict__ Wi_w, const float* __restrict__ Wi_b,
                       const float* __restrict__ Ws_w, const float* __restrict__ Ws_b,
                       const float* __restrict__ Wh_b,
                       const float* __restrict__ att_irr, const float* __restrict__ att_sol) {
    int c = threadIdx.x;  // 0..127
    float v1i = 0.f, v2i = 0.f, v1s = 0.f, v2s = 0.f;
    for (int j = 0; j < 2; j++) {
        for (int o = 0; o < 128; o++) {
            int a = j * 128 + o;
            float wi = Wi_w[(j * 128 + c) * 128 + o];
            float ws = Ws_w[(j * 128 + c) * 128 + o];
            v1i += wi * att_irr[a];       v2i += wi * att_irr[256 + a];
            v1s += ws * att_sol[a];       v2s += ws * att_sol[256 + a];
        }
    }
    g_v[0][c] = v1i; g_v[1][c] = v2i; g_v[2][c] = v1s; g_v[3][c] = v2s;

    float c1i = 0.f, c2i = 0.f, c1s = 0.f, c2s = 0.f;
    for (int j = 0; j < 2; j++) {
        int a = j * 128 + c;
        c1i += Wi_b[a] * att_irr[a];  c2i += Wi_b[a] * att_irr[256 + a];
        c1s += Ws_b[a] * att_sol[a];  c2s += Ws_b[a] * att_sol[256 + a];
    }
    __shared__ float red[4][128];
    red[0][c] = c1i; red[1][c] = c2i; red[2][c] = c1s; red[3][c] = c2s;
    __syncthreads();
    for (int s = 64; s > 0; s >>= 1) {
        if (c < s) {
            for (int q = 0; q < 4; q++) red[q][c] += red[q][c + s];
        }
        __syncthreads();
    }
    if (c < 4) g_c[c] = red[c][0];
    g_bias[c] = Wi_b[c] + Wi_b[128 + c] + Ws_b[c] + Ws_b[128 + c] + Wh_b[c];
}

// ---------------- kernel 2: per-node scores s = x @ v + c ----------------
__global__ void k_scores(const float* __restrict__ x) {
    int i = blockIdx.x, t = threadIdx.x;
    float xv = x[(size_t)i * 128 + t];
    __shared__ float red[4][128];
    red[0][t] = xv * g_v[0][t];
    red[1][t] = xv * g_v[1][t];
    red[2][t] = xv * g_v[2][t];
    red[3][t] = xv * g_v[3][t];
    __syncthreads();
    for (int s = 64; s > 0; s >>= 1) {
        if (t < s) {
            for (int q = 0; q < 4; q++) red[q][t] += red[q][t + s];
        }
        __syncthreads();
    }
    if (t < 4) g_s[t][i] = red[t][0] + g_c[t];
}

// ---------------- kernel 3: sparse L@x + row max of masked leaky scores ----------------
__global__ __launch_bounds__(128) void k_spmm(const float* __restrict__ L, const float* __restrict__ x,
                                              const float* __restrict__ s1, const float* __restrict__ s2,
                                              float* __restrict__ Lx, float* __restrict__ rowmax) {
    int i = blockIdx.x, t = threadIdx.x;
    float s1i = s1[i];
    float acc = 0.f, mmax = -INFINITY;
    __shared__ int s_idx[128];
    __shared__ float s_val[128];
    __shared__ int s_cnt;
    for (int j0 = 0; j0 < N_ROWS; j0 += 128) {
        if (t == 0) s_cnt = 0;
        __syncthreads();
        float lv = L[(size_t)i * N_ROWS + j0 + t];
        if (lv != 0.f) {
            float e = s1i + s2[j0 + t];
            e = (e >= 0.f) ? e : 0.2f * e;
            mmax = fmaxf(mmax, e);
            int p = atomicAdd(&s_cnt, 1);
            s_idx[p] = j0 + t;
            s_val[p] = lv;
        }
        __syncthreads();
        int c = s_cnt;
        for (int p = 0; p < c; p++) acc += s_val[p] * x[(size_t)s_idx[p] * 128 + t];
        __syncthreads();
    }
    Lx[(size_t)i * 128 + t] = acc;
    __shared__ float rmx[128];
    rmx[t] = mmax;
    __syncthreads();
    for (int s = 64; s > 0; s >>= 1) {
        if (t < s) rmx[t] = fmaxf(rmx[t], rmx[t + s]);
        __syncthreads();
    }
    if (t == 0) rowmax[i] = rmx[0];
}

// ---------------- kernel 4: dense P@x, SIMT fp32, split-K=2 ----------------
__global__ __launch_bounds__(256) void k_gemm_px(const float* __restrict__ A, const float* __restrict__ B,
                                                 float* __restrict__ C) {
    __shared__ float As[32][65];   // [k][m], padded conflict-free
    __shared__ float Bs[32][128];
    int tid = threadIdx.x;
    int bm = blockIdx.x * 64;
    int kbeg = blockIdx.y * 2048;
    int trow = (tid >> 5) * 8;
    int tcol = (tid & 31) * 4;
    int am = tid >> 3;            // 0..31 (rows am and am+32)
    int ak = (tid & 7) * 4;
    int br = tid >> 5;            // 0..7
    int bc = (tid & 31) * 4;
    float acc[8][4];
#pragma unroll
    for (int r = 0; r < 8; r++)
#pragma unroll
        for (int c = 0; c < 4; c++) acc[r][c] = 0.f;

    for (int kk = kbeg; kk < kbeg + 2048; kk += 32) {
        float4 av0 = *(const float4*)&A[(size_t)(bm + am) * N_ROWS + kk + ak];
        float4 av1 = *(const float4*)&A[(size_t)(bm + am + 32) * N_ROWS + kk + ak];
        As[ak + 0][am] = av0.x; As[ak + 1][am] = av0.y; As[ak + 2][am] = av0.z; As[ak + 3][am] = av0.w;
        As[ak + 0][am + 32] = av1.x; As[ak + 1][am + 32] = av1.y; As[ak + 2][am + 32] = av1.z; As[ak + 3][am + 32] = av1.w;
#pragma unroll
        for (int q = 0; q < 4; q++)
            *(float4*)&Bs[br + q * 8][bc] = *(const float4*)&B[(size_t)(kk + br + q * 8) * 128 + bc];
        __syncthreads();
#pragma unroll
        for (int k = 0; k < 32; k++) {
            float a[8];
#pragma unroll
            for (int r = 0; r < 8; r++) a[r] = As[k][trow + r];
            float4 bv = *(float4*)&Bs[k][tcol];
#pragma unroll
            for (int r = 0; r < 8; r++) {
                acc[r][0] += a[r] * bv.x;
                acc[r][1] += a[r] * bv.y;
                acc[r][2] += a[r] * bv.z;
                acc[r][3] += a[r] * bv.w;
            }
        }
        __syncthreads();
    }
    float* Cs = C + (size_t)blockIdx.y * N_ROWS * 128;
#pragma unroll
    for (int r = 0; r < 8; r++) {
        float4 o = make_float4(acc[r][0], acc[r][1], acc[r][2], acc[r][3]);
        *(float4*)&Cs[(size_t)(bm + trow + r) * 128 + tcol] = o;
    }
}

// ---------------- kernel 5: C = A1@W1 + A2@W2 (+bias), K=128 ----------------
template <bool ADD_BIAS>
__global__ __launch_bounds__(256) void k_gemm2(const float* __restrict__ A1, const float* __restrict__ A2,
                                               const float* __restrict__ W1, const float* __restrict__ W2,
                                               float* __restrict__ C) {
    __shared__ float A1s[32][33];
    __shared__ float A2s[32][33];
    __shared__ float W1s[32][128];
    __shared__ float W2s[32][128];
    int tid = threadIdx.x;
    int bm = blockIdx.x * 32;
    int trow = (tid >> 5) * 4;
    int tcol = (tid & 31) * 4;
    int am = tid >> 3;          // 0..31
    int ak = (tid & 7) * 4;
    int wr = tid >> 5;          // 0..7
    int wc = (tid & 31) * 4;
    float acc[4][4];
#pragma unroll
    for (int r = 0; r < 4; r++)
#pragma unroll
        for (int c = 0; c < 4; c++) acc[r][c] = 0.f;

    for (int kk = 0; kk < 128; kk += 32) {
        float4 a1 = *(const float4*)&A1[(size_t)(bm + am) * 128 + kk + ak];
        float4 a2 = *(const float4*)&A2[(size_t)(bm + am) * 128 + kk + ak];
        A1s[ak + 0][am] = a1.x; A1s[ak + 1][am] = a1.y; A1s[ak + 2][am] = a1.z; A1s[ak + 3][am] = a1.w;
        A2s[ak + 0][am] = a2.x; A2s[ak + 1][am] = a2.y; A2s[ak + 2][am] = a2.z; A2s[ak + 3][am] = a2.w;
#pragma unroll
        for (int q = 0; q < 4; q++) {
            *(float4*)&W1s[wr + q * 8][wc] = *(const float4*)&W1[(size_t)(kk + wr + q * 8) * 128 + wc];
            *(float4*)&W2s[wr + q * 8][wc] = *(const float4*)&W2[(size_t)(kk + wr + q * 8) * 128 + wc];
        }
        __syncthreads();
#pragma unroll
        for (int k = 0; k < 32; k++) {
            float a1f[4], a2f[4];
#pragma unroll
            for (int r = 0; r < 4; r++) { a1f[r] = A1s[k][trow + r]; a2f[r] = A2s[k][trow + r]; }
            float4 w1v = *(float4*)&W1s[k][tcol];
            float4 w2v = *(float4*)&W2s[k][tcol];
#pragma unroll
            for (int r = 0; r < 4; r++) {
                acc[r][0] += a1f[r] * w1v.x + a2f[r] * w2v.x;
                acc[r][1] += a1f[r] * w1v.y + a2f[r] * w2v.y;
                acc[r][2] += a1f[r] * w1v.z + a2f[r] * w2v.z;
                acc[r][3] += a1f[r] * w1v.w + a2f[r] * w2v.w;
            }
        }
        __syncthreads();
    }
#pragma unroll
    for (int r = 0; r < 4; r++) {
        float4 o = make_float4(acc[r][0], acc[r][1], acc[r][2], acc[r][3]);
        if (ADD_BIAS) {
            o.x += g_bias[tcol + 0];
            o.y += g_bias[tcol + 1];
            o.z += g_bias[tcol + 2];
            o.w += g_bias[tcol + 3];
        }
        *(float4*)&C[(size_t)(bm + trow + r) * 128 + tcol] = o;
    }
}

// ---------------- kernel 6: z += softmax_row(mask(leaky(s1+s2))) @ M ----------------
__global__ __launch_bounds__(128) void k_attn(const float* __restrict__ L, const float* __restrict__ M,
                                              const float* __restrict__ s1, const float* __restrict__ s2,
                                              const float* __restrict__ rowmax, float* __restrict__ z) {
    int i = blockIdx.x, t = threadIdx.x;
    float s1i = s1[i];
    float m = rowmax[i];
    bool allm = !(m > -1e30f);  // entire row masked -> uniform softmax
    float acc = 0.f, dpart = 0.f;
    __shared__ int s_idx[128];
    __shared__ float s_w[128];
    __shared__ int s_cnt;
    for (int j0 = 0; j0 < N_ROWS; j0 += 128) {
        if (t == 0) s_cnt = 0;
        __syncthreads();
        float lv = L[(size_t)i * N_ROWS + j0 + t];
        float w = 0.f;
        if (allm) {
            w = 1.f;
        } else if (lv != 0.f) {
            float e = s1i + s2[j0 + t];
            e = (e >= 0.f) ? e : 0.2f * e;
            w = __expf(e - m);
        }
        if (w != 0.f) {
            dpart += w;
            int p = atomicAdd(&s_cnt, 1);
            s_idx[p] = j0 + t;
            s_w[p] = w;
        }
        __syncthreads();
        int c = s_cnt;
        for (int p = 0; p < c; p++) acc += s_w[p] * M[(size_t)s_idx[p] * 128 + t];
        __syncthreads();
    }
    __shared__ float red[128];
    red[t] = dpart;
    __syncthreads();
    for (int s = 64; s > 0; s >>= 1) {
        if (t < s) red[t] += red[t + s];
        __syncthreads();
    }
    float d = red[0];
    z[(size_t)i * 128 + t] += acc / d;
}

// ---------------- host launcher ----------------
extern "C" void kernel_launch(void* const* d_in, const int* in_sizes, int n_in,
                              void* d_out, int out_size) {
    const float* x       = (const float*)d_in[0];
    const float* Lu      = (const float*)d_in[1];
    const float* Ld      = (const float*)d_in[2];
    const float* P       = (const float*)d_in[3];
    const float* Wi_w    = (const float*)d_in[4];
    const float* Wi_b    = (const float*)d_in[5];
    const float* Ws_w    = (const float*)d_in[6];
    const float* Ws_b    = (const float*)d_in[7];
    const float* Wh_w    = (const float*)d_in[8];
    const float* Wh_b    = (const float*)d_in[9];
    const float* att_irr = (const float*)d_in[10];
    const float* att_sol = (const float*)d_in[11];
    float* z = (float*)d_out;

    float *p_s, *p_Ldx, *p_Lux, *p_Px, *p_Mirr, *p_Msol, *p_rowmax;
    cudaGetSymbolAddress((void**)&p_s, g_s);
    cudaGetSymbolAddress((void**)&p_Ldx, g_Ldx);
    cudaGetSymbolAddress((void**)&p_Lux, g_Lux);
    cudaGetSymbolAddress((void**)&p_Px, g_Px);
    cudaGetSymbolAddress((void**)&p_Mirr, g_Mirr);
    cudaGetSymbolAddress((void**)&p_Msol, g_Msol);
    cudaGetSymbolAddress((void**)&p_rowmax, g_rowmax);

    k_prep<<<1, 128>>>(Wi_w, Wi_b, Ws_w, Ws_b, Wh_b, att_irr, att_sol);
    k_scores<<<N_ROWS, 128>>>(x);

    // sparse Laplacian*x + attention row maxes
    k_spmm<<<N_ROWS, 128>>>(Ld, x, p_s + 0 * N_ROWS, p_s + 1 * N_ROWS, p_Ldx, p_rowmax);
    k_spmm<<<N_ROWS, 128>>>(Lu, x, p_s + 2 * N_ROWS, p_s + 3 * N_ROWS, p_Lux, p_rowmax + N_ROWS);

    // dense P @ x (split-K = 2)
    k_gemm_px<<<dim3(N_ROWS / 64, 2), 256>>>(P, x, p_Px);

    // M_irr = x@Wi0 + (Ld@x)@Wi1 ;  M_sol = x@Ws0 + (Lu@x)@Ws1
    k_gemm2<false><<<N_ROWS / 32, 256>>>(x, p_Ldx, Wi_w, Wi_w + 128 * 128, p_Mirr);
    k_gemm2<false><<<N_ROWS / 32, 256>>>(x, p_Lux, Ws_w, Ws_w + 128 * 128, p_Msol);
    // z = (Px0 + Px1)@Wh + total_bias   (same W applied to both split-K slabs)
    k_gemm2<true><<<N_ROWS / 32, 256>>>(p_Px, p_Px + N_ROWS * 128, Wh_w, Wh_w, z);

    // z += softmax(Ld-masked) @ M_irr ;  z += softmax(Lu-masked) @ M_sol
    k_attn<<<N_ROWS, 128>>>(Ld, p_Mirr, p_s + 0 * N_ROWS, p_s + 1 * N_ROWS, p_rowmax, z);
    k_attn<<<N_ROWS, 128>>>(Lu, p_Msol, p_s + 2 * N_ROWS, p_s + 3 * N_ROWS, p_rowmax + N_ROWS, z);
}